// round 4
// baseline (speedup 1.0000x reference)
#include <cuda_runtime.h>
#include <cuda_bf16.h>
#include <mma.h>
#include <cstdint>

using namespace nvcuda;

#define BATCH   4
#define T_SEQ   64
#define NSPAT   196
#define CDIM    768
#define HEADS   12
#define HD      64
#define M_TOT   (BATCH * T_SEQ * NSPAT)   // 50176
#define QKV_N   (3 * CDIM)                // 2304

// Scratch (device globals: allocation-free per harness rules)
__device__ float g_qkv[(size_t)M_TOT * QKV_N];   // 462 MB
__device__ float g_att[(size_t)M_TOT * CDIM];    // 154 MB

// ---------------------------------------------------------------------------
// TF32 WMMA GEMM, 4-stage cp.async pipeline, 512 threads (16 warps).
// C[m][n] = sum_k A[m*K+k] * B[n*K+k]  (+ optional bias[n])
// Block tile 128x128, BK=32. Warp grid 4(m) x 4(n), warp tile 32x32
// = 2x2 fragments of 16x16x8.
// ---------------------------------------------------------------------------
#define BM 128
#define BN 128
#define BK 32
#define STAGES 4
#define LDS_T 36                          // smem row stride (floats), 144B
#define STAGE_F (2 * 128 * LDS_T)         // floats per stage (A then B)
#define LDC_S 132                         // epilogue staging stride
#define GEMM_SMEM (STAGES * STAGE_F * 4)  // 147,456 B

__device__ __forceinline__ void cp_async16(uint32_t saddr, const void* gptr) {
    asm volatile("cp.async.cg.shared.global [%0], [%1], 16;\n" :: "r"(saddr), "l"(gptr));
}
__device__ __forceinline__ void cp_commit() {
    asm volatile("cp.async.commit_group;\n" ::: "memory");
}
__device__ __forceinline__ void cp_wait2() {
    asm volatile("cp.async.wait_group 2;\n" ::: "memory");
}

__global__ void __launch_bounds__(512, 1) gemm_tf32_pipe_kernel(
    const float* __restrict__ A, const float* __restrict__ B,
    float* __restrict__ C, const float* __restrict__ bias,
    int M, int N, int K)
{
    extern __shared__ float smem[];

    const int n0 = blockIdx.x * BN;          // N fastest -> weight resident in L2
    const int m0 = blockIdx.y * BM;

    const int tid  = threadIdx.x;
    const int warp = tid >> 5;
    const int wm   = warp >> 2;   // 0..3  -> rows wm*32
    const int wn   = warp & 3;    // 0..3  -> cols wn*32

    // loader mapping: 1024 float4 per operand per stage; 512 threads x 2 iters
    const int ldrow = tid >> 2;              // 0..127
    const int ldk4  = (tid & 3) * 2;         // 0,2,4,6 (two consecutive float4)

    wmma::fragment<wmma::accumulator, 16, 16, 8, float> acc[2][2];
    #pragma unroll
    for (int i = 0; i < 2; i++)
        #pragma unroll
        for (int j = 0; j < 2; j++)
            wmma::fill_fragment(acc[i][j], 0.0f);

    const int NB = K / BK;   // 24 or 24

    auto issue_stage = [&](int kb, int stg) {
        float* As = smem + stg * STAGE_F;
        float* Bs = As + 128 * LDS_T;
        const float* Ag = A + (size_t)(m0 + ldrow) * K + kb * BK + ldk4 * 4;
        const float* Bg = B + (size_t)(n0 + ldrow) * K + kb * BK + ldk4 * 4;
        uint32_t sa = (uint32_t)__cvta_generic_to_shared(&As[ldrow * LDS_T + ldk4 * 4]);
        uint32_t sb = (uint32_t)__cvta_generic_to_shared(&Bs[ldrow * LDS_T + ldk4 * 4]);
        cp_async16(sa,      Ag);
        cp_async16(sa + 16, Ag + 4);
        cp_async16(sb,      Bg);
        cp_async16(sb + 16, Bg + 4);
    };

    // prologue: stages 0..2
    issue_stage(0, 0); cp_commit();
    issue_stage(1, 1); cp_commit();
    issue_stage(2, 2); cp_commit();

    for (int kb = 0; kb < NB; kb++) {
        cp_wait2();            // stage kb resident
        __syncthreads();       // also protects the buffer being refilled

        if (kb + 3 < NB) issue_stage(kb + 3, (kb + 3) & 3);
        cp_commit();           // exactly one group per iteration

        const float* a_st = smem + (kb & 3) * STAGE_F;
        const float* b_st = a_st + 128 * LDS_T;

        #pragma unroll
        for (int kk = 0; kk < BK; kk += 8) {
            wmma::fragment<wmma::matrix_a, 16, 16, 8, wmma::precision::tf32, wmma::row_major> af[2];
            wmma::fragment<wmma::matrix_b, 16, 16, 8, wmma::precision::tf32, wmma::col_major> bf[2];
            #pragma unroll
            for (int i = 0; i < 2; i++) {
                wmma::load_matrix_sync(af[i], &a_st[(wm * 32 + i * 16) * LDS_T + kk], LDS_T);
                #pragma unroll
                for (int t = 0; t < af[i].num_elements; t++)
                    af[i].x[t] = wmma::__float_to_tf32(af[i].x[t]);
            }
            #pragma unroll
            for (int j = 0; j < 2; j++) {
                wmma::load_matrix_sync(bf[j], &b_st[(wn * 32 + j * 16) * LDS_T + kk], LDS_T);
                #pragma unroll
                for (int t = 0; t < bf[j].num_elements; t++)
                    bf[j].x[t] = wmma::__float_to_tf32(bf[j].x[t]);
            }
            #pragma unroll
            for (int i = 0; i < 2; i++)
                #pragma unroll
                for (int j = 0; j < 2; j++)
                    wmma::mma_sync(acc[i][j], af[i], bf[j], acc[i][j]);
        }
        __syncthreads();
    }

    // ---- epilogue: stage through smem, fused bias, coalesced float4 stores ----
    float* sC = smem;   // 128 * LDC_S floats = 67.6KB
    #pragma unroll
    for (int i = 0; i < 2; i++)
        #pragma unroll
        for (int j = 0; j < 2; j++)
            wmma::store_matrix_sync(&sC[(wm * 32 + i * 16) * LDC_S + wn * 32 + j * 16],
                                    acc[i][j], LDC_S, wmma::mem_row_major);
    __syncthreads();

    #pragma unroll
    for (int it = 0; it < 8; it++) {
        int idx = tid + it * 512;         // 4096 float4 total
        int row = idx >> 5;               // 0..127
        int c4  = idx & 31;               // 0..31
        float4 v = *(float4*)&sC[row * LDC_S + c4 * 4];
        if (bias) {
            float4 bv = *(const float4*)&bias[n0 + c4 * 4];
            v.x += bv.x; v.y += bv.y; v.z += bv.z; v.w += bv.w;
        }
        *(float4*)&C[(size_t)(m0 + row) * N + n0 + c4 * 4] = v;
    }
}

// ---------------------------------------------------------------------------
// Causal attention per (b,h,n): T=64, hd=64. 256 threads, 4x4 per-thread tiles.
// ---------------------------------------------------------------------------
#define LDT 68   // transposed-tile row stride (floats)

__global__ void __launch_bounds__(256) attn_kernel(
    const float* __restrict__ qkv, float* __restrict__ att)
{
    extern __shared__ float smemf[];
    float* sQ = smemf;                 // [d][t] stride LDT
    float* sK = smemf + 64 * LDT;      // [d][t] stride LDT
    float* sV = smemf + 2 * 64 * LDT;  // [t][d] stride 64
    float* sP = sQ;                    // reused: [j][i] stride LDT

    const int blk = blockIdx.x;        // n + NSPAT*(h + HEADS*b)
    const int n = blk % NSPAT;
    const int h = (blk / NSPAT) % HEADS;
    const int b = blk / (NSPAT * HEADS);

    const int tid = threadIdx.x;
    const size_t rowstride = (size_t)NSPAT * QKV_N;
    const size_t base = ((size_t)b * T_SEQ * NSPAT + n) * QKV_N + (size_t)h * HD;

    for (int idx = tid; idx < 64 * 64; idx += 256) {
        int t = idx >> 6;
        int d = idx & 63;
        size_t g = base + (size_t)t * rowstride;
        sQ[d * LDT + t] = qkv[g + d];
        sK[d * LDT + t] = qkv[g + CDIM + d];
        sV[t * 64 + d]  = qkv[g + 2 * CDIM + d];
    }
    __syncthreads();

    const int ti = tid >> 4;
    const int tj = tid & 15;

    float accS[16];
    #pragma unroll
    for (int i = 0; i < 16; i++) accS[i] = 0.0f;

    #pragma unroll 4
    for (int d = 0; d < 64; d++) {
        float4 a4 = *(const float4*)&sQ[d * LDT + 4 * ti];
        float4 b4 = *(const float4*)&sK[d * LDT + 4 * tj];
        float av[4] = {a4.x, a4.y, a4.z, a4.w};
        float bv[4] = {b4.x, b4.y, b4.z, b4.w};
        #pragma unroll
        for (int ii = 0; ii < 4; ii++)
            #pragma unroll
            for (int jj = 0; jj < 4; jj++)
                accS[ii * 4 + jj] += av[ii] * bv[jj];
    }

    const float scale = 0.125f;   // hd^-0.5
    #pragma unroll
    for (int ii = 0; ii < 4; ii++) {
        int i = 4 * ti + ii;
        float mx = -3.402823466e38f;
        #pragma unroll
        for (int jj = 0; jj < 4; jj++) {
            int j = 4 * tj + jj;
            float s = (j <= i) ? accS[ii * 4 + jj] * scale : -3.402823466e38f;
            accS[ii * 4 + jj] = s;
            mx = fmaxf(mx, s);
        }
        #pragma unroll
        for (int m = 8; m >= 1; m >>= 1)
            mx = fmaxf(mx, __shfl_xor_sync(0xffffffffu, mx, m));
        float sum = 0.0f;
        #pragma unroll
        for (int jj = 0; jj < 4; jj++) {
            float e = __expf(accS[ii * 4 + jj] - mx);
            accS[ii * 4 + jj] = e;
            sum += e;
        }
        #pragma unroll
        for (int m = 8; m >= 1; m >>= 1)
            sum += __shfl_xor_sync(0xffffffffu, sum, m);
        float inv = 1.0f / sum;
        #pragma unroll
        for (int jj = 0; jj < 4; jj++) accS[ii * 4 + jj] *= inv;
    }

    __syncthreads();
    #pragma unroll
    for (int ii = 0; ii < 4; ii++)
        #pragma unroll
        for (int jj = 0; jj < 4; jj++)
            sP[(4 * tj + jj) * LDT + 4 * ti + ii] = accS[ii * 4 + jj];
    __syncthreads();

    float o[16];
    #pragma unroll
    for (int i = 0; i < 16; i++) o[i] = 0.0f;

    #pragma unroll 4
    for (int j = 0; j < 64; j++) {
        float4 p4 = *(const float4*)&sP[j * LDT + 4 * ti];
        float4 v4 = *(const float4*)&sV[j * 64 + 4 * tj];
        float pv[4] = {p4.x, p4.y, p4.z, p4.w};
        float vv[4] = {v4.x, v4.y, v4.z, v4.w};
        #pragma unroll
        for (int ii = 0; ii < 4; ii++)
            #pragma unroll
            for (int jj = 0; jj < 4; jj++)
                o[ii * 4 + jj] += pv[ii] * vv[jj];
    }

    #pragma unroll
    for (int ii = 0; ii < 4; ii++) {
        int i = 4 * ti + ii;
        size_t addr = (((size_t)b * T_SEQ + i) * NSPAT + n) * CDIM + (size_t)h * HD + 4 * tj;
        float4 o4 = make_float4(o[ii * 4 + 0], o[ii * 4 + 1], o[ii * 4 + 2], o[ii * 4 + 3]);
        *(float4*)&att[addr] = o4;
    }
}

// ---------------------------------------------------------------------------
extern "C" void kernel_launch(void* const* d_in, const int* in_sizes, int n_in,
                              void* d_out, int out_size)
{
    const float* x      = (const float*)d_in[0];
    const float* w_qkv  = (const float*)d_in[1];
    const float* w_proj = (const float*)d_in[2];
    const float* b_proj = (const float*)d_in[3];
    float* out = (float*)d_out;

    float *qkv_buf, *att_buf;
    cudaGetSymbolAddress((void**)&qkv_buf, g_qkv);
    cudaGetSymbolAddress((void**)&att_buf, g_att);

    const int attn_smem = 2 * 64 * LDT * 4 + 64 * 64 * 4;  // 51,200 B
    static bool attr_done = false;
    if (!attr_done) {
        cudaFuncSetAttribute(gemm_tf32_pipe_kernel,
                             cudaFuncAttributeMaxDynamicSharedMemorySize, GEMM_SMEM);
        cudaFuncSetAttribute(attn_kernel,
                             cudaFuncAttributeMaxDynamicSharedMemorySize, attn_smem);
        attr_done = true;
    }

    // 1) QKV GEMM: (50176 x 768) @ (2304 x 768)^T
    {
        dim3 grid(QKV_N / BN, M_TOT / BM);   // (18, 392)
        gemm_tf32_pipe_kernel<<<grid, 512, GEMM_SMEM>>>(
            x, w_qkv, qkv_buf, nullptr, M_TOT, QKV_N, CDIM);
    }
    // 2) Attention: one block per (b,h,n)
    {
        dim3 grid(BATCH * HEADS * NSPAT);    // 9408
        attn_kernel<<<grid, 256, attn_smem>>>(qkv_buf, att_buf);
    }
    // 3) Projection GEMM + fused bias: (50176 x 768) @ (768 x 768)^T -> d_out
    {
        dim3 grid(CDIM / BN, M_TOT / BM);    // (6, 392)
        gemm_tf32_pipe_kernel<<<grid, 512, GEMM_SMEM>>>(
            att_buf, w_proj, out, b_proj, M_TOT, CDIM, CDIM);
    }
}

// round 5
// speedup vs baseline: 2.2153x; 2.2153x over previous
#include <cuda_runtime.h>
#include <cuda_bf16.h>
#include <cstdint>

#define BATCH   4
#define T_SEQ   64
#define NSPAT   196
#define CDIM    768
#define HEADS   12
#define HD      64
#define M_TOT   (BATCH * T_SEQ * NSPAT)   // 50176
#define QKV_N   (3 * CDIM)                // 2304

// Scratch (device globals: allocation-free per harness rules)
__device__ float g_qkv[(size_t)M_TOT * QKV_N];   // 462 MB
__device__ float g_att[(size_t)M_TOT * CDIM];    // 154 MB
__device__ float g_xr [(size_t)M_TOT * CDIM];    // tf32-rounded x
__device__ float g_wq [(size_t)QKV_N * CDIM];    // tf32-rounded w_qkv
__device__ float g_wp [(size_t)CDIM * CDIM];     // tf32-rounded w_proj

// ---------------------------------------------------------------------------
// helpers
// ---------------------------------------------------------------------------
__device__ __forceinline__ void cp_async16(uint32_t saddr, const void* gptr) {
    asm volatile("cp.async.cg.shared.global [%0], [%1], 16;\n" :: "r"(saddr), "l"(gptr));
}
__device__ __forceinline__ void cp_commit() {
    asm volatile("cp.async.commit_group;\n" ::: "memory");
}
__device__ __forceinline__ void cp_wait1() {
    asm volatile("cp.async.wait_group 1;\n" ::: "memory");
}
__device__ __forceinline__ float f2tf32(float x) {
    float r;
    asm("cvt.rna.tf32.f32 %0, %1;" : "=f"(r) : "f"(x));
    return r;
}
// D += A*B  (m16n8k8, tf32 bits in registers)
__device__ __forceinline__ void mma1688(float* d, const uint32_t* a, const uint32_t* b) {
    asm volatile(
        "mma.sync.aligned.m16n8k8.row.col.f32.tf32.tf32.f32 "
        "{%0,%1,%2,%3}, {%4,%5,%6,%7}, {%8,%9}, {%0,%1,%2,%3};"
        : "+f"(d[0]), "+f"(d[1]), "+f"(d[2]), "+f"(d[3])
        : "r"(a[0]), "r"(a[1]), "r"(a[2]), "r"(a[3]), "r"(b[0]), "r"(b[1]));
}

// ---------------------------------------------------------------------------
// Raw-PTX TF32 GEMM: C[m][n] = sum_k A[m*K+k] * B[n*K+k] (+ bias[n])
// Block 128(m) x 256(n), BK=32, 3-stage cp.async, 256 threads = 8 warps (2x4),
// warp tile 64x64 = 4(m-frag) x 8(n-frag) of m16n8k8.
// Inputs must be pre-rounded to tf32 (bits fed directly to mma).
// ---------------------------------------------------------------------------
#define GBM 128
#define GBN 256
#define GBK 32
#define G_LDS 36                                // row stride floats (144B)
#define G_STAGE_F ((GBM + GBN) * G_LDS)         // 13,824 floats = 55,296 B
#define G_STAGES 3
#define G_SMEM (G_STAGES * G_STAGE_F * 4)       // 165,888 B

__global__ void __launch_bounds__(256, 1) gemm_mma_kernel(
    const float* __restrict__ A, const float* __restrict__ B,
    float* __restrict__ C, const float* __restrict__ bias,
    int M, int N, int K)
{
    extern __shared__ float smem[];

    const int n0 = blockIdx.x * GBN;     // N fastest -> weights L2-resident
    const int m0 = blockIdx.y * GBM;

    const int tid  = threadIdx.x;
    const int warp = tid >> 5;
    const int lane = tid & 31;
    const int wm   = warp >> 2;          // 0..1 -> rows wm*64
    const int wn   = warp & 3;           // 0..3 -> cols wn*64
    const int g    = lane >> 2;          // 0..7
    const int t    = lane & 3;           // 0..3

    float acc[4][8][4];
    #pragma unroll
    for (int i = 0; i < 4; i++)
        #pragma unroll
        for (int j = 0; j < 8; j++)
            #pragma unroll
            for (int c = 0; c < 4; c++)
                acc[i][j][c] = 0.0f;

    const int NB = K / GBK;

    // stage loader: 3072 float4 chunks (A rows 0..127, B rows 128..383)
    auto issue_stage = [&](int kb, int s) {
        float* dst = smem + s * G_STAGE_F;
        #pragma unroll
        for (int i = 0; i < 12; i++) {
            int id = tid + i * 256;              // 0..3071
            int r  = id >> 3;                    // 0..383
            int c  = id & 7;                     // 0..7
            const float* gp = (r < GBM)
                ? A + (size_t)(m0 + r) * K + kb * GBK + c * 4
                : B + (size_t)(n0 + r - GBM) * K + kb * GBK + c * 4;
            uint32_t sa = (uint32_t)__cvta_generic_to_shared(&dst[r * G_LDS + c * 4]);
            cp_async16(sa, gp);
        }
    };

    issue_stage(0, 0); cp_commit();
    issue_stage(1, 1); cp_commit();

    for (int kb = 0; kb < NB; kb++) {
        cp_wait1();            // stage kb resident
        __syncthreads();       // all threads' data visible; prev compute done

        if (kb + 2 < NB) issue_stage(kb + 2, (kb + 2) % 3);
        cp_commit();           // exactly one group per iteration

        const uint32_t* As = (const uint32_t*)(smem + (kb % 3) * G_STAGE_F);
        const uint32_t* Bs = As + GBM * G_LDS;

        #pragma unroll
        for (int k0 = 0; k0 < GBK; k0 += 8) {
            uint32_t a[4][4];
            #pragma unroll
            for (int mf = 0; mf < 4; mf++) {
                int r = (wm * 64 + mf * 16 + g) * G_LDS + k0 + t;
                a[mf][0] = As[r];
                a[mf][1] = As[r + 8 * G_LDS];
                a[mf][2] = As[r + 4];
                a[mf][3] = As[r + 8 * G_LDS + 4];
            }
            uint32_t b[8][2];
            #pragma unroll
            for (int nf = 0; nf < 8; nf++) {
                int r = (wn * 64 + nf * 8 + g) * G_LDS + k0 + t;
                b[nf][0] = Bs[r];
                b[nf][1] = Bs[r + 4];
            }
            #pragma unroll
            for (int mf = 0; mf < 4; mf++)
                #pragma unroll
                for (int nf = 0; nf < 8; nf++)
                    mma1688(acc[mf][nf], a[mf], b[nf]);
        }
    }

    // direct register epilogue, fused bias, float2 stores
    #pragma unroll
    for (int nf = 0; nf < 8; nf++) {
        int col = n0 + wn * 64 + nf * 8 + 2 * t;
        float2 bv = make_float2(0.0f, 0.0f);
        if (bias) bv = *(const float2*)&bias[col];
        #pragma unroll
        for (int mf = 0; mf < 4; mf++) {
            int row = m0 + wm * 64 + mf * 16 + g;
            float2 v0 = make_float2(acc[mf][nf][0] + bv.x, acc[mf][nf][1] + bv.y);
            float2 v1 = make_float2(acc[mf][nf][2] + bv.x, acc[mf][nf][3] + bv.y);
            *(float2*)&C[(size_t)row * N + col]       = v0;
            *(float2*)&C[(size_t)(row + 8) * N + col] = v1;
        }
    }
}

// ---------------------------------------------------------------------------
// tf32 rounding prepass (RN)
// ---------------------------------------------------------------------------
__global__ void __launch_bounds__(256) round_tf32_kernel(
    const float* __restrict__ in, float* __restrict__ out, size_t n4)
{
    size_t i = (size_t)blockIdx.x * 256 + threadIdx.x;
    if (i < n4) {
        float4 v = ((const float4*)in)[i];
        v.x = f2tf32(v.x); v.y = f2tf32(v.y); v.z = f2tf32(v.z); v.w = f2tf32(v.w);
        ((float4*)out)[i] = v;
    }
}

// ---------------------------------------------------------------------------
// Causal attention per (b,h,n): T=64, hd=64. 256 threads, 4x4 per-thread tiles.
// Outputs rounded to tf32 (feed raw-bits GEMM3).
// ---------------------------------------------------------------------------
#define LDT 68

__global__ void __launch_bounds__(256) attn_kernel(
    const float* __restrict__ qkv, float* __restrict__ att)
{
    extern __shared__ float smemf[];
    float* sQ = smemf;
    float* sK = smemf + 64 * LDT;
    float* sV = smemf + 2 * 64 * LDT;
    float* sP = sQ;

    const int blk = blockIdx.x;
    const int n = blk % NSPAT;
    const int h = (blk / NSPAT) % HEADS;
    const int b = blk / (NSPAT * HEADS);

    const int tid = threadIdx.x;
    const size_t rowstride = (size_t)NSPAT * QKV_N;
    const size_t base = ((size_t)b * T_SEQ * NSPAT + n) * QKV_N + (size_t)h * HD;

    for (int idx = tid; idx < 64 * 64; idx += 256) {
        int t = idx >> 6;
        int d = idx & 63;
        size_t gaddr = base + (size_t)t * rowstride;
        sQ[d * LDT + t] = qkv[gaddr + d];
        sK[d * LDT + t] = qkv[gaddr + CDIM + d];
        sV[t * 64 + d]  = qkv[gaddr + 2 * CDIM + d];
    }
    __syncthreads();

    const int ti = tid >> 4;
    const int tj = tid & 15;

    float accS[16];
    #pragma unroll
    for (int i = 0; i < 16; i++) accS[i] = 0.0f;

    #pragma unroll 4
    for (int d = 0; d < 64; d++) {
        float4 a4 = *(const float4*)&sQ[d * LDT + 4 * ti];
        float4 b4 = *(const float4*)&sK[d * LDT + 4 * tj];
        float av[4] = {a4.x, a4.y, a4.z, a4.w};
        float bv[4] = {b4.x, b4.y, b4.z, b4.w};
        #pragma unroll
        for (int ii = 0; ii < 4; ii++)
            #pragma unroll
            for (int jj = 0; jj < 4; jj++)
                accS[ii * 4 + jj] += av[ii] * bv[jj];
    }

    const float scale = 0.125f;
    #pragma unroll
    for (int ii = 0; ii < 4; ii++) {
        int i = 4 * ti + ii;
        float mx = -3.402823466e38f;
        #pragma unroll
        for (int jj = 0; jj < 4; jj++) {
            int j = 4 * tj + jj;
            float s = (j <= i) ? accS[ii * 4 + jj] * scale : -3.402823466e38f;
            accS[ii * 4 + jj] = s;
            mx = fmaxf(mx, s);
        }
        #pragma unroll
        for (int m = 8; m >= 1; m >>= 1)
            mx = fmaxf(mx, __shfl_xor_sync(0xffffffffu, mx, m));
        float sum = 0.0f;
        #pragma unroll
        for (int jj = 0; jj < 4; jj++) {
            float e = __expf(accS[ii * 4 + jj] - mx);
            accS[ii * 4 + jj] = e;
            sum += e;
        }
        #pragma unroll
        for (int m = 8; m >= 1; m >>= 1)
            sum += __shfl_xor_sync(0xffffffffu, sum, m);
        float inv = 1.0f / sum;
        #pragma unroll
        for (int jj = 0; jj < 4; jj++) accS[ii * 4 + jj] *= inv;
    }

    __syncthreads();
    #pragma unroll
    for (int ii = 0; ii < 4; ii++)
        #pragma unroll
        for (int jj = 0; jj < 4; jj++)
            sP[(4 * tj + jj) * LDT + 4 * ti + ii] = accS[ii * 4 + jj];
    __syncthreads();

    float o[16];
    #pragma unroll
    for (int i = 0; i < 16; i++) o[i] = 0.0f;

    #pragma unroll 4
    for (int j = 0; j < 64; j++) {
        float4 p4 = *(const float4*)&sP[j * LDT + 4 * ti];
        float4 v4 = *(const float4*)&sV[j * 64 + 4 * tj];
        float pv[4] = {p4.x, p4.y, p4.z, p4.w};
        float vv[4] = {v4.x, v4.y, v4.z, v4.w};
        #pragma unroll
        for (int ii = 0; ii < 4; ii++)
            #pragma unroll
            for (int jj = 0; jj < 4; jj++)
                o[ii * 4 + jj] += pv[ii] * vv[jj];
    }

    #pragma unroll
    for (int ii = 0; ii < 4; ii++) {
        int i = 4 * ti + ii;
        size_t addr = (((size_t)b * T_SEQ + i) * NSPAT + n) * CDIM + (size_t)h * HD + 4 * tj;
        float4 o4 = make_float4(f2tf32(o[ii * 4 + 0]), f2tf32(o[ii * 4 + 1]),
                                f2tf32(o[ii * 4 + 2]), f2tf32(o[ii * 4 + 3]));
        *(float4*)&att[addr] = o4;
    }
}

// ---------------------------------------------------------------------------
extern "C" void kernel_launch(void* const* d_in, const int* in_sizes, int n_in,
                              void* d_out, int out_size)
{
    const float* x      = (const float*)d_in[0];
    const float* w_qkv  = (const float*)d_in[1];
    const float* w_proj = (const float*)d_in[2];
    const float* b_proj = (const float*)d_in[3];
    float* out = (float*)d_out;

    float *qkv_buf, *att_buf, *xr, *wq, *wp;
    cudaGetSymbolAddress((void**)&qkv_buf, g_qkv);
    cudaGetSymbolAddress((void**)&att_buf, g_att);
    cudaGetSymbolAddress((void**)&xr, g_xr);
    cudaGetSymbolAddress((void**)&wq, g_wq);
    cudaGetSymbolAddress((void**)&wp, g_wp);

    const int attn_smem = 2 * 64 * LDT * 4 + 64 * 64 * 4;  // 51,200 B
    static bool attr_done = false;
    if (!attr_done) {
        cudaFuncSetAttribute(gemm_mma_kernel,
                             cudaFuncAttributeMaxDynamicSharedMemorySize, G_SMEM);
        cudaFuncSetAttribute(attn_kernel,
                             cudaFuncAttributeMaxDynamicSharedMemorySize, attn_smem);
        attr_done = true;
    }

    // 0) tf32 rounding prepasses (x and both weights)
    {
        size_t n4 = (size_t)M_TOT * CDIM / 4;
        round_tf32_kernel<<<(unsigned)((n4 + 255) / 256), 256>>>(x, xr, n4);
        size_t wq4 = (size_t)QKV_N * CDIM / 4;
        round_tf32_kernel<<<(unsigned)((wq4 + 255) / 256), 256>>>(w_qkv, wq, wq4);
        size_t wp4 = (size_t)CDIM * CDIM / 4;
        round_tf32_kernel<<<(unsigned)((wp4 + 255) / 256), 256>>>(w_proj, wp, wp4);
    }
    // 1) QKV GEMM: (50176 x 768) @ (2304 x 768)^T
    {
        dim3 grid(QKV_N / GBN, M_TOT / GBM);   // (9, 392)
        gemm_mma_kernel<<<grid, 256, G_SMEM>>>(xr, wq, qkv_buf, nullptr,
                                               M_TOT, QKV_N, CDIM);
    }
    // 2) Attention
    {
        dim3 grid(BATCH * HEADS * NSPAT);      // 9408
        attn_kernel<<<grid, 256, attn_smem>>>(qkv_buf, att_buf);
    }
    // 3) Projection GEMM + fused bias
    {
        dim3 grid(CDIM / GBN, M_TOT / GBM);    // (3, 392)
        gemm_mma_kernel<<<grid, 256, G_SMEM>>>(att_buf, wp, out, b_proj,
                                               M_TOT, CDIM, CDIM);
    }
}